// round 11
// baseline (speedup 1.0000x reference)
#include <cuda_runtime.h>
#include <cuda_bf16.h>
#include <cstdint>

#define N_NODES 100000
#define N_EDGES 1600000
#define HID 64
#define NGRAPH 128
#define DENSE 128
#define SCAN_BLK 4096
#define NB ((N_NODES + SCAN_BLK - 1) / SCAN_BLK)   // 25 blocks (all co-resident)

// Scratch
__device__ float           g_buf0[N_NODES * HID];  // fp32 h (layer-2 agg out, pool input)
__device__ __nv_bfloat16   g_hb[N_NODES * HID];    // bf16 h (gemm input)
__device__ __nv_bfloat16   g_gath[N_NODES * HID];  // (h@W)*dinv, bf16 gather buffer
__device__ int    g_cnt[N_NODES];                  // zeroed at end of fill_k each call
__device__ int    g_rowptr[N_NODES + 1];
__device__ int    g_cursor[N_NODES];
__device__ int    g_col[N_EDGES];
__device__ float  g_dinv[N_NODES];
__device__ float4 g_xd[N_NODES];                   // x * dinv[src], padded
__device__ unsigned long long g_aggflag[NB];       // (1<<40)|aggregate; zeroed in fill_k

#define AGG_FLAG (1ull << 40)

// ---------------------------------------------------------------- CSR build
__global__ void hist_k(const int* __restrict__ ei) {
    int i = blockIdx.x * blockDim.x + threadIdx.x;
    if (i < N_EDGES / 4) {
        int4 d = ((const int4*)(ei + N_EDGES))[i];
        atomicAdd(&g_cnt[d.x], 1);
        atomicAdd(&g_cnt[d.y], 1);
        atomicAdd(&g_cnt[d.z], 1);
        atomicAdd(&g_cnt[d.w], 1);
    }
}

// Single-pass scan: local exclusive scan + cross-block offset via flagged
// aggregates (all NB=25 blocks co-resident -> no deadlock).
__global__ void scan_k(const float* __restrict__ x) {
    __shared__ int sh[1024];
    __shared__ int off_s;
    int tid = threadIdx.x;
    int bid = blockIdx.x;
    int base = bid * SCAN_BLK;
    int v[4];
    int local = 0;
#pragma unroll
    for (int q = 0; q < 4; q++) {
        int i = base + tid * 4 + q;
        v[q] = (i < N_NODES) ? g_cnt[i] : 0;
        local += v[q];
    }
    sh[tid] = local;
    for (int off = 1; off < 1024; off <<= 1) {
        __syncthreads();
        int t = (tid >= off) ? sh[tid - off] : 0;
        __syncthreads();
        sh[tid] += t;
    }
    __syncthreads();
    int total = sh[1023];

    if (tid < 32) {
        if (tid == 0) {
            __threadfence();
            g_aggflag[bid] = AGG_FLAG | (unsigned long long)total;
        }
        unsigned long long av = 0;
        if (tid < bid) {
            volatile unsigned long long* p = &g_aggflag[tid];
            do { av = *p; } while (!(av & AGG_FLAG));
        }
        int pre = (int)(av & 0xFFFFFFFFull);
#pragma unroll
        for (int o = 16; o; o >>= 1) pre += __shfl_xor_sync(0xffffffffu, pre, o);
        if (tid == 0) off_s = pre;
    }
    __syncthreads();
    int run = off_s + sh[tid] - local;
#pragma unroll
    for (int q = 0; q < 4; q++) {
        int i = base + tid * 4 + q;
        if (i < N_NODES) {
            g_rowptr[i] = run;
            g_cursor[i] = run;
            run += v[q];
            float di = rsqrtf((float)(v[q] + 1));   // +1 self loop
            g_dinv[i] = di;
            float x0 = x[i * 3 + 0], x1 = x[i * 3 + 1], x2 = x[i * 3 + 2];
            g_xd[i] = make_float4(x0 * di, x1 * di, x2 * di, 0.f);
        }
    }
    if (bid == NB - 1 && tid == 1023) g_rowptr[N_NODES] = run;
}

// Cursor-based fill, 4 edges per thread; re-zeroes g_cnt + aggflags at tail.
__global__ void fill_k(const int* __restrict__ ei) {
    int i = blockIdx.x * blockDim.x + threadIdx.x;
    if (i < N_EDGES / 4) {
        int4 s = ((const int4*)ei)[i];
        int4 d = ((const int4*)(ei + N_EDGES))[i];
        g_col[atomicAdd(&g_cursor[d.x], 1)] = s.x;
        g_col[atomicAdd(&g_cursor[d.y], 1)] = s.y;
        g_col[atomicAdd(&g_cursor[d.z], 1)] = s.z;
        g_col[atomicAdd(&g_cursor[d.w], 1)] = s.w;
    }
    if (i < N_NODES / 4) ((int4*)g_cnt)[i] = make_int4(0, 0, 0, 0);
    if (i < NB) g_aggflag[i] = 0ull;
}

// ---------------------------------------------------------------- Layer 0 (fused)
// 8 lanes per node: gather-reduce xd (3ch), then emit bf16 relu(aggx@W0+b0).
__global__ void agg_x_gemm0_k(const float* __restrict__ W0, const float* __restrict__ b0) {
    __shared__ float Ws[3 * HID];
    __shared__ float Bs[HID];
    int t = threadIdx.x;
    if (t < 3 * HID) Ws[t] = W0[t];
    if (t < HID) Bs[t] = b0[t];
    __syncthreads();
    int node = (blockIdx.x * blockDim.x + t) >> 3;
    int l8   = t & 7;
    if (node >= N_NODES) return;
    int s = g_rowptr[node];
    int e = g_rowptr[node + 1];
    float ax = 0.f, ay = 0.f, az = 0.f;
    if (l8 == 0) { float4 v = g_xd[node]; ax = v.x; ay = v.y; az = v.z; }
    for (int idx = s + l8; idx < e; idx += 8) {
        float4 v = g_xd[g_col[idx]];
        ax += v.x; ay += v.y; az += v.z;
    }
#pragma unroll
    for (int off = 1; off < 8; off <<= 1) {
        ax += __shfl_xor_sync(0xffffffffu, ax, off);
        ay += __shfl_xor_sync(0xffffffffu, ay, off);
        az += __shfl_xor_sync(0xffffffffu, az, off);
    }
    float di = g_dinv[node];
    ax *= di; ay *= di; az *= di;
    int c0 = l8 * 8;
    float o[8];
#pragma unroll
    for (int q = 0; q < 8; q++) {
        int c = c0 + q;
        o[q] = fmaxf(fmaf(ax, Ws[c], fmaf(ay, Ws[HID + c], fmaf(az, Ws[2 * HID + c], Bs[c]))), 0.f);
    }
    __nv_bfloat162 p0 = __floats2bfloat162_rn(o[0], o[1]);
    __nv_bfloat162 p1 = __floats2bfloat162_rn(o[2], o[3]);
    __nv_bfloat162 p2 = __floats2bfloat162_rn(o[4], o[5]);
    __nv_bfloat162 p3 = __floats2bfloat162_rn(o[6], o[7]);
    uint4 pk;
    pk.x = *(uint32_t*)&p0; pk.y = *(uint32_t*)&p1;
    pk.z = *(uint32_t*)&p2; pk.w = *(uint32_t*)&p3;
    *(uint4*)&g_hb[node * HID + c0] = pk;
}

// ---------------------------------------------------------------- GEMM (tensor core)
// g_gath[r] = bf16( (hb @ W)[r] * dinv[r] ), hb bf16, W fp32->bf16, fp32 accum.
#define AS_LD 72   // bf16 stride (64 + 8 pad)
__global__ void gemm64_k(const float* __restrict__ W) {
    __shared__ __nv_bfloat16 As[128 * AS_LD];
    __shared__ __nv_bfloat16 Wsm[64 * AS_LD];
    int t = threadIdx.x;
    int warp = t >> 5, lane = t & 31;
    int rb = blockIdx.x * 128;

#pragma unroll
    for (int q = 0; q < 16; q++) {
        int i = t + q * 256;
        int r = i >> 6, c = i & 63;
        Wsm[r * AS_LD + c] = __float2bfloat16(W[i]);
    }
#pragma unroll
    for (int q = 0; q < 4; q++) {
        int i = t + q * 256;
        int r = i >> 3, seg = i & 7;
        uint4 v = make_uint4(0, 0, 0, 0);
        if (rb + r < N_NODES) v = ((const uint4*)&g_hb[(rb + r) * HID])[seg];
        *(uint4*)&As[r * AS_LD + seg * 8] = v;
    }
    __syncthreads();

    int wrow = warp * 16;
    float acc[8][4];
#pragma unroll
    for (int nb = 0; nb < 8; nb++)
#pragma unroll
        for (int q = 0; q < 4; q++) acc[nb][q] = 0.f;

#pragma unroll
    for (int ks = 0; ks < 4; ks++) {
        uint32_t a0, a1, a2, a3;
        {
            const __nv_bfloat16* ap = &As[(wrow + (lane & 15)) * AS_LD + ks * 16 + (lane >> 4) * 8];
            uint32_t addr = (uint32_t)__cvta_generic_to_shared(ap);
            asm volatile("ldmatrix.sync.aligned.m8n8.x4.shared.b16 {%0,%1,%2,%3}, [%4];"
                         : "=r"(a0), "=r"(a1), "=r"(a2), "=r"(a3) : "r"(addr));
        }
#pragma unroll
        for (int nb = 0; nb < 8; nb++) {
            uint32_t b0, b1;
            const __nv_bfloat16* bp = &Wsm[(ks * 16 + (lane & 15)) * AS_LD + nb * 8];
            uint32_t baddr = (uint32_t)__cvta_generic_to_shared(bp);
            asm volatile("ldmatrix.sync.aligned.m8n8.x2.trans.shared.b16 {%0,%1}, [%2];"
                         : "=r"(b0), "=r"(b1) : "r"(baddr));
            asm volatile(
                "mma.sync.aligned.m16n8k16.row.col.f32.bf16.bf16.f32 "
                "{%0,%1,%2,%3},{%4,%5,%6,%7},{%8,%9},{%0,%1,%2,%3};"
                : "+f"(acc[nb][0]), "+f"(acc[nb][1]), "+f"(acc[nb][2]), "+f"(acc[nb][3])
                : "r"(a0), "r"(a1), "r"(a2), "r"(a3), "r"(b0), "r"(b1));
        }
    }

    int r0 = rb + wrow + (lane >> 2);
    int r1 = r0 + 8;
    float di0 = (r0 < N_NODES) ? g_dinv[r0] : 0.f;
    float di1 = (r1 < N_NODES) ? g_dinv[r1] : 0.f;
    int cb = (lane & 3) * 2;
#pragma unroll
    for (int nb = 0; nb < 8; nb++) {
        int c = nb * 8 + cb;
        if (r0 < N_NODES) {
            __nv_bfloat162 p = __floats2bfloat162_rn(acc[nb][0] * di0, acc[nb][1] * di0);
            *(uint32_t*)&g_gath[r0 * HID + c] = *(uint32_t*)&p;
        }
        if (r1 < N_NODES) {
            __nv_bfloat162 p = __floats2bfloat162_rn(acc[nb][2] * di1, acc[nb][3] * di1);
            *(uint32_t*)&g_gath[r1 * HID + c] = *(uint32_t*)&p;
        }
    }
}

// ---------------------------------------------------------------- Aggregation
// TWO warps per dst node (32 channels each); 4 edge-groups x 8 lanes x 4 ch.
// uint2 (8B) bf16 loads, fp32 accumulate, direct g_col loads.
template <bool OUT_BF16>
__global__ void agg_k(const float* __restrict__ bias) {
    int gw   = (blockIdx.x * blockDim.x + threadIdx.x) >> 5;
    int w    = gw >> 1;
    int half = gw & 1;
    int lane = threadIdx.x & 31;
    if (w >= N_NODES) return;
    int grp = lane >> 3;
    int l8  = lane & 7;
    int ch0 = half * 32 + l8 * 4;
    int s = g_rowptr[w];
    int e = g_rowptr[w + 1];

    float2 a0 = make_float2(0.f, 0.f), a1 = a0;

#define ACC_ROW(SRC)                                                          \
    {                                                                         \
        uint2 pk = *(const uint2*)&g_gath[(SRC) * HID + ch0];                 \
        float2 f0 = __bfloat1622float2(*(__nv_bfloat162*)&pk.x);              \
        float2 f1 = __bfloat1622float2(*(__nv_bfloat162*)&pk.y);              \
        a0.x += f0.x; a0.y += f0.y; a1.x += f1.x; a1.y += f1.y;               \
    }

    int idx = s + grp;
    for (; idx + 12 < e; idx += 16) {      // 4 edges per group in flight
        int s0 = g_col[idx];
        int s1 = g_col[idx + 4];
        int s2 = g_col[idx + 8];
        int s3 = g_col[idx + 12];
        ACC_ROW(s0); ACC_ROW(s1); ACC_ROW(s2); ACC_ROW(s3);
    }
    for (; idx < e; idx += 4) {
        int s0 = g_col[idx];
        ACC_ROW(s0);
    }
#undef ACC_ROW

#pragma unroll
    for (int off = 8; off <= 16; off <<= 1) {
        a0.x += __shfl_xor_sync(0xffffffffu, a0.x, off);
        a0.y += __shfl_xor_sync(0xffffffffu, a0.y, off);
        a1.x += __shfl_xor_sync(0xffffffffu, a1.x, off);
        a1.y += __shfl_xor_sync(0xffffffffu, a1.y, off);
    }

    if (grp == 0) {
        uint2 pk = *(const uint2*)&g_gath[w * HID + ch0];   // self loop
        float2 f0 = __bfloat1622float2(*(__nv_bfloat162*)&pk.x);
        float2 f1 = __bfloat1622float2(*(__nv_bfloat162*)&pk.y);
        a0.x += f0.x; a0.y += f0.y; a1.x += f1.x; a1.y += f1.y;

        float di = g_dinv[w];
        float4 bA = *(const float4*)&bias[ch0];
        float o0 = fmaxf(fmaf(a0.x, di, bA.x), 0.f);
        float o1 = fmaxf(fmaf(a0.y, di, bA.y), 0.f);
        float o2 = fmaxf(fmaf(a1.x, di, bA.z), 0.f);
        float o3 = fmaxf(fmaf(a1.y, di, bA.w), 0.f);
        if (OUT_BF16) {
            __nv_bfloat162 p0 = __floats2bfloat162_rn(o0, o1);
            __nv_bfloat162 p1 = __floats2bfloat162_rn(o2, o3);
            uint2 pko;
            pko.x = *(uint32_t*)&p0; pko.y = *(uint32_t*)&p1;
            *(uint2*)&g_hb[w * HID + ch0] = pko;
        } else {
            *(float4*)&g_buf0[w * HID + ch0] = make_float4(o0, o1, o2, o3);
        }
    }
}

// ---------------------------------------------------------------- Pool + head (fused)
__global__ void poolfc_k(const int* __restrict__ batch,
                         const float* __restrict__ fc1w, const float* __restrict__ fc1b,
                         const float* __restrict__ fc2w, const float* __restrict__ fc2b,
                         float* __restrict__ out) {
    int g = blockIdx.x, t = threadIdx.x;   // 128 blocks x 256 thr
    __shared__ int lo_s, hi_s;
    if (t == 0) {
        int lo = 0, hi = N_NODES;
        while (lo < hi) { int m = (lo + hi) >> 1; if (batch[m] < g) lo = m + 1; else hi = m; }
        lo_s = lo;
        int lo2 = lo, hi2 = N_NODES;
        while (lo2 < hi2) { int m = (lo2 + hi2) >> 1; if (batch[m] < g + 1) lo2 = m + 1; else hi2 = m; }
        hi_s = lo2;
    }
    __syncthreads();
    int lo = lo_s, hi = hi_s;
    int c = t & 63, rg = t >> 6;
    float acc = 0.f;
    for (int r = lo + rg; r < hi; r += 4) acc += g_buf0[r * HID + c];
    __shared__ float sh[256];
    __shared__ float p[64];
    sh[t] = acc;
    __syncthreads();
    if (t < 64) {
        float s = sh[t] + sh[t + 64] + sh[t + 128] + sh[t + 192];
        float cntf = (float)(hi - lo);
        if (cntf < 1.f) cntf = 1.f;
        p[t] = s / cntf;
    }
    __syncthreads();
    float v = 0.f;
    if (t < DENSE) {
        float a = fc1b[t];
#pragma unroll
        for (int k = 0; k < 64; k++) a = fmaf(p[k], fc1w[k * DENSE + t], a);
        v = fmaxf(a, 0.f) * fc2w[t];
    }
    __syncthreads();
    sh[t] = v;
    __syncthreads();
    if (t < 64) sh[t] += sh[t + 64];
    __syncthreads();
    if (t < 32) {
        float s = sh[t] + sh[t + 32];
#pragma unroll
        for (int off = 16; off; off >>= 1) s += __shfl_down_sync(0xffffffffu, s, off);
        if (t == 0) out[g] = s + fc2b[0];
    }
}

// ---------------------------------------------------------------- launch
extern "C" void kernel_launch(void* const* d_in, const int* in_sizes, int n_in,
                              void* d_out, int out_size) {
    const float* x     = (const float*)d_in[0];
    const int*   ei    = (const int*)d_in[1];
    const int*   batch = (const int*)d_in[2];
    const float* W0    = (const float*)d_in[3];
    const float* b0    = (const float*)d_in[4];
    const float* W1    = (const float*)d_in[5];
    const float* b1    = (const float*)d_in[6];
    const float* W2    = (const float*)d_in[7];
    const float* b2    = (const float*)d_in[8];
    const float* fc1w  = (const float*)d_in[9];
    const float* fc1b  = (const float*)d_in[10];
    const float* fc2w  = (const float*)d_in[11];
    const float* fc2b  = (const float*)d_in[12];
    float* out = (float*)d_out;

    // CSR build (g_cnt and g_aggflag enter zeroed: zero-init at load,
    // re-zeroed by fill_k each call)
    hist_k<<<(N_EDGES / 4 + 255) / 256, 256>>>(ei);
    scan_k<<<NB, 1024>>>(x);
    fill_k<<<(N_EDGES / 4 + 255) / 256, 256>>>(ei);

    const int AGG_BLOCKS  = (N_NODES * 64 + 255) / 256;   // 2 warps per node
    const int GEMM_BLOCKS = (N_NODES + 127) / 128;

    // Layer 0 (fused 3-ch aggregate + dense, bf16 out)
    agg_x_gemm0_k<<<(N_NODES * 8 + 255) / 256, 256>>>(W0, b0);
    // Layer 1
    gemm64_k<<<GEMM_BLOCKS, 256>>>(W1);
    agg_k<true><<<AGG_BLOCKS, 256>>>(b1);
    // Layer 2
    gemm64_k<<<GEMM_BLOCKS, 256>>>(W2);
    agg_k<false><<<AGG_BLOCKS, 256>>>(b2);

    // Pool + head
    poolfc_k<<<NGRAPH, 256>>>(batch, fc1w, fc1b, fc2w, fc2b, out);
}

// round 12
// speedup vs baseline: 1.1510x; 1.1510x over previous
#include <cuda_runtime.h>
#include <cuda_bf16.h>
#include <cstdint>

#define N_NODES 100000
#define N_EDGES 1600000
#define HID 64
#define NGRAPH 128
#define DENSE 128
#define CSR_BLOCKS 148
#define CSR_THREADS 256
#define NB2 ((N_NODES + 1023) / 1024)   // 98 scan chunks (1024 nodes each)

// Scratch
__device__ float           g_buf0[N_NODES * HID];  // fp32 h (layer-2 agg out, pool input)
__device__ __nv_bfloat16   g_hb[N_NODES * HID];    // bf16 h (gemm input)
__device__ __nv_bfloat16   g_gath[N_NODES * HID];  // (h@W)*dinv, bf16 gather buffer
__device__ int    g_cnt[N_NODES];                  // zeroed at end of csr_k each call
__device__ int    g_rowptr[N_NODES + 1];
__device__ int    g_cursor[N_NODES];
__device__ int    g_col[N_EDGES];
__device__ float  g_dinv[N_NODES];
__device__ float4 g_xd[N_NODES];                   // x * dinv[src], padded
__device__ int    g_bsum[NB2];
__device__ unsigned int g_bar_count;               // grid barrier (self-resetting)
__device__ unsigned int g_bar_gen;

// Generation-counting grid barrier. All CSR_BLOCKS co-resident (1 block/SM).
__device__ __forceinline__ void grid_barrier() {
    __syncthreads();
    if (threadIdx.x == 0) {
        __threadfence();
        unsigned int gen = *((volatile unsigned int*)&g_bar_gen);
        unsigned int t = atomicAdd(&g_bar_count, 1u);
        if (t == CSR_BLOCKS - 1) {
            g_bar_count = 0u;
            __threadfence();
            atomicAdd(&g_bar_gen, 1u);
        } else {
            while (*((volatile unsigned int*)&g_bar_gen) == gen) { }
        }
        __threadfence();
    }
    __syncthreads();
}

// ---------------------------------------------------------------- Fused CSR build
// Phase 1: histogram (REDG). Phase 2: scan + dinv/xd/cursor. Phase 3: fill + cnt zero.
__global__ void __launch_bounds__(CSR_THREADS, 1) csr_k(const int* __restrict__ ei,
                                                        const float* __restrict__ x) {
    int tid = threadIdx.x, bid = blockIdx.x;
    const int stride = CSR_BLOCKS * CSR_THREADS;
    const int nitems = N_EDGES / 4;

    // ---- Phase 1: histogram, 4 edges per item
    for (int i = bid * CSR_THREADS + tid; i < nitems; i += stride) {
        int4 d = ((const int4*)(ei + N_EDGES))[i];
        atomicAdd(&g_cnt[d.x], 1);
        atomicAdd(&g_cnt[d.y], 1);
        atomicAdd(&g_cnt[d.z], 1);
        atomicAdd(&g_cnt[d.w], 1);
    }
    grid_barrier();

    // ---- Phase 2a: block-local exclusive scan (blocks 0..NB2-1, 1024 nodes each)
    __shared__ int sh[CSR_THREADS];
    __shared__ int sb[128];
    int v[4];
    int local = 0;
    int base = bid * 1024;
    if (bid < NB2) {
#pragma unroll
        for (int q = 0; q < 4; q++) {
            int i = base + tid * 4 + q;
            v[q] = (i < N_NODES) ? g_cnt[i] : 0;
            local += v[q];
        }
        sh[tid] = local;
        for (int off = 1; off < CSR_THREADS; off <<= 1) {
            __syncthreads();
            int t = (tid >= off) ? sh[tid - off] : 0;
            __syncthreads();
            sh[tid] += t;
        }
        __syncthreads();
        if (tid == CSR_THREADS - 1) g_bsum[bid] = sh[CSR_THREADS - 1];
    }
    grid_barrier();

    // ---- Phase 2b: cross-block prefix + write rowptr/cursor/dinv/xd
    if (bid < NB2) {
        if (tid < 128) sb[tid] = (tid < bid) ? g_bsum[tid] : 0;   // NB2=98 <= 128
        __syncthreads();
#pragma unroll
        for (int off = 64; off >= 1; off >>= 1) {
            if (tid < off) sb[tid] += sb[tid + off];
            __syncthreads();
        }
        int pre = sb[0];
        int run = pre + sh[tid] - local;
#pragma unroll
        for (int q = 0; q < 4; q++) {
            int i = base + tid * 4 + q;
            if (i < N_NODES) {
                g_rowptr[i] = run;
                g_cursor[i] = run;
                run += v[q];
                float di = rsqrtf((float)(v[q] + 1));   // +1 self loop
                g_dinv[i] = di;
                float x0 = x[i * 3 + 0], x1 = x[i * 3 + 1], x2 = x[i * 3 + 2];
                g_xd[i] = make_float4(x0 * di, x1 * di, x2 * di, 0.f);
            }
        }
        if (bid == NB2 - 1 && tid == CSR_THREADS - 1) g_rowptr[N_NODES] = run;
    }
    grid_barrier();

    // ---- Phase 3: cursor fill + re-zero g_cnt for the next call
    for (int i = bid * CSR_THREADS + tid; i < nitems; i += stride) {
        int4 s = ((const int4*)ei)[i];
        int4 d = ((const int4*)(ei + N_EDGES))[i];
        g_col[atomicAdd(&g_cursor[d.x], 1)] = s.x;
        g_col[atomicAdd(&g_cursor[d.y], 1)] = s.y;
        g_col[atomicAdd(&g_cursor[d.z], 1)] = s.z;
        g_col[atomicAdd(&g_cursor[d.w], 1)] = s.w;
    }
    for (int i = bid * CSR_THREADS + tid; i < N_NODES / 4; i += stride)
        ((int4*)g_cnt)[i] = make_int4(0, 0, 0, 0);
}

// ---------------------------------------------------------------- Layer 0 (fused)
// 8 lanes per node: gather-reduce xd (3ch), then emit bf16 relu(aggx@W0+b0).
__global__ void agg_x_gemm0_k(const float* __restrict__ W0, const float* __restrict__ b0) {
    __shared__ float Ws[3 * HID];
    __shared__ float Bs[HID];
    int t = threadIdx.x;
    if (t < 3 * HID) Ws[t] = W0[t];
    if (t < HID) Bs[t] = b0[t];
    __syncthreads();
    int node = (blockIdx.x * blockDim.x + t) >> 3;
    int l8   = t & 7;
    if (node >= N_NODES) return;
    int s = g_rowptr[node];
    int e = g_rowptr[node + 1];
    float ax = 0.f, ay = 0.f, az = 0.f;
    if (l8 == 0) { float4 v = g_xd[node]; ax = v.x; ay = v.y; az = v.z; }
    for (int idx = s + l8; idx < e; idx += 8) {
        float4 v = g_xd[g_col[idx]];
        ax += v.x; ay += v.y; az += v.z;
    }
#pragma unroll
    for (int off = 1; off < 8; off <<= 1) {
        ax += __shfl_xor_sync(0xffffffffu, ax, off);
        ay += __shfl_xor_sync(0xffffffffu, ay, off);
        az += __shfl_xor_sync(0xffffffffu, az, off);
    }
    float di = g_dinv[node];
    ax *= di; ay *= di; az *= di;
    int c0 = l8 * 8;
    float o[8];
#pragma unroll
    for (int q = 0; q < 8; q++) {
        int c = c0 + q;
        o[q] = fmaxf(fmaf(ax, Ws[c], fmaf(ay, Ws[HID + c], fmaf(az, Ws[2 * HID + c], Bs[c]))), 0.f);
    }
    __nv_bfloat162 p0 = __floats2bfloat162_rn(o[0], o[1]);
    __nv_bfloat162 p1 = __floats2bfloat162_rn(o[2], o[3]);
    __nv_bfloat162 p2 = __floats2bfloat162_rn(o[4], o[5]);
    __nv_bfloat162 p3 = __floats2bfloat162_rn(o[6], o[7]);
    uint4 pk;
    pk.x = *(uint32_t*)&p0; pk.y = *(uint32_t*)&p1;
    pk.z = *(uint32_t*)&p2; pk.w = *(uint32_t*)&p3;
    *(uint4*)&g_hb[node * HID + c0] = pk;
}

// ---------------------------------------------------------------- GEMM (tensor core)
// g_gath[r] = bf16( (hb @ W)[r] * dinv[r] ), hb bf16, W fp32->bf16, fp32 accum.
#define AS_LD 72   // bf16 stride (64 + 8 pad)
__global__ void gemm64_k(const float* __restrict__ W) {
    __shared__ __nv_bfloat16 As[128 * AS_LD];
    __shared__ __nv_bfloat16 Wsm[64 * AS_LD];
    int t = threadIdx.x;
    int warp = t >> 5, lane = t & 31;
    int rb = blockIdx.x * 128;

#pragma unroll
    for (int q = 0; q < 16; q++) {
        int i = t + q * 256;
        int r = i >> 6, c = i & 63;
        Wsm[r * AS_LD + c] = __float2bfloat16(W[i]);
    }
#pragma unroll
    for (int q = 0; q < 4; q++) {
        int i = t + q * 256;
        int r = i >> 3, seg = i & 7;
        uint4 v = make_uint4(0, 0, 0, 0);
        if (rb + r < N_NODES) v = ((const uint4*)&g_hb[(rb + r) * HID])[seg];
        *(uint4*)&As[r * AS_LD + seg * 8] = v;
    }
    __syncthreads();

    int wrow = warp * 16;
    float acc[8][4];
#pragma unroll
    for (int nb = 0; nb < 8; nb++)
#pragma unroll
        for (int q = 0; q < 4; q++) acc[nb][q] = 0.f;

#pragma unroll
    for (int ks = 0; ks < 4; ks++) {
        uint32_t a0, a1, a2, a3;
        {
            const __nv_bfloat16* ap = &As[(wrow + (lane & 15)) * AS_LD + ks * 16 + (lane >> 4) * 8];
            uint32_t addr = (uint32_t)__cvta_generic_to_shared(ap);
            asm volatile("ldmatrix.sync.aligned.m8n8.x4.shared.b16 {%0,%1,%2,%3}, [%4];"
                         : "=r"(a0), "=r"(a1), "=r"(a2), "=r"(a3) : "r"(addr));
        }
#pragma unroll
        for (int nb = 0; nb < 8; nb++) {
            uint32_t b0, b1;
            const __nv_bfloat16* bp = &Wsm[(ks * 16 + (lane & 15)) * AS_LD + nb * 8];
            uint32_t baddr = (uint32_t)__cvta_generic_to_shared(bp);
            asm volatile("ldmatrix.sync.aligned.m8n8.x2.trans.shared.b16 {%0,%1}, [%2];"
                         : "=r"(b0), "=r"(b1) : "r"(baddr));
            asm volatile(
                "mma.sync.aligned.m16n8k16.row.col.f32.bf16.bf16.f32 "
                "{%0,%1,%2,%3},{%4,%5,%6,%7},{%8,%9},{%0,%1,%2,%3};"
                : "+f"(acc[nb][0]), "+f"(acc[nb][1]), "+f"(acc[nb][2]), "+f"(acc[nb][3])
                : "r"(a0), "r"(a1), "r"(a2), "r"(a3), "r"(b0), "r"(b1));
        }
    }

    int r0 = rb + wrow + (lane >> 2);
    int r1 = r0 + 8;
    float di0 = (r0 < N_NODES) ? g_dinv[r0] : 0.f;
    float di1 = (r1 < N_NODES) ? g_dinv[r1] : 0.f;
    int cb = (lane & 3) * 2;
#pragma unroll
    for (int nb = 0; nb < 8; nb++) {
        int c = nb * 8 + cb;
        if (r0 < N_NODES) {
            __nv_bfloat162 p = __floats2bfloat162_rn(acc[nb][0] * di0, acc[nb][1] * di0);
            *(uint32_t*)&g_gath[r0 * HID + c] = *(uint32_t*)&p;
        }
        if (r1 < N_NODES) {
            __nv_bfloat162 p = __floats2bfloat162_rn(acc[nb][2] * di1, acc[nb][3] * di1);
            *(uint32_t*)&g_gath[r1 * HID + c] = *(uint32_t*)&p;
        }
    }
}

// ---------------------------------------------------------------- Aggregation (R10 form)
// One warp per dst node; 4 groups x 8 lanes, direct g_col loads, uint4 bf16 rows,
// fp32 accumulate.
template <bool OUT_BF16>
__global__ void agg_k(const float* __restrict__ bias) {
    int w    = (blockIdx.x * blockDim.x + threadIdx.x) >> 5;
    int lane = threadIdx.x & 31;
    if (w >= N_NODES) return;
    int grp = lane >> 3;
    int l8  = lane & 7;
    int ch0 = l8 * 8;
    int s = g_rowptr[w];
    int e = g_rowptr[w + 1];

    float2 a0 = make_float2(0.f, 0.f), a1 = a0, a2 = a0, a3 = a0;

#define ACC_ROW(SRC)                                                          \
    {                                                                         \
        uint4 pk = *(const uint4*)&g_gath[(SRC) * HID + ch0];                 \
        float2 f0 = __bfloat1622float2(*(__nv_bfloat162*)&pk.x);              \
        float2 f1 = __bfloat1622float2(*(__nv_bfloat162*)&pk.y);              \
        float2 f2 = __bfloat1622float2(*(__nv_bfloat162*)&pk.z);              \
        float2 f3 = __bfloat1622float2(*(__nv_bfloat162*)&pk.w);              \
        a0.x += f0.x; a0.y += f0.y; a1.x += f1.x; a1.y += f1.y;               \
        a2.x += f2.x; a2.y += f2.y; a3.x += f3.x; a3.y += f3.y;               \
    }

    int idx = s + grp;
    for (; idx + 12 < e; idx += 16) {      // 4 edges per group in flight
        int s0 = g_col[idx];
        int s1 = g_col[idx + 4];
        int s2 = g_col[idx + 8];
        int s3 = g_col[idx + 12];
        ACC_ROW(s0); ACC_ROW(s1); ACC_ROW(s2); ACC_ROW(s3);
    }
    for (; idx < e; idx += 4) {
        int s0 = g_col[idx];
        ACC_ROW(s0);
    }
#undef ACC_ROW

#pragma unroll
    for (int off = 8; off <= 16; off <<= 1) {
        a0.x += __shfl_xor_sync(0xffffffffu, a0.x, off);
        a0.y += __shfl_xor_sync(0xffffffffu, a0.y, off);
        a1.x += __shfl_xor_sync(0xffffffffu, a1.x, off);
        a1.y += __shfl_xor_sync(0xffffffffu, a1.y, off);
        a2.x += __shfl_xor_sync(0xffffffffu, a2.x, off);
        a2.y += __shfl_xor_sync(0xffffffffu, a2.y, off);
        a3.x += __shfl_xor_sync(0xffffffffu, a3.x, off);
        a3.y += __shfl_xor_sync(0xffffffffu, a3.y, off);
    }

    if (grp == 0) {
        uint4 pk = *(const uint4*)&g_gath[w * HID + ch0];   // self loop
        float2 f0 = __bfloat1622float2(*(__nv_bfloat162*)&pk.x);
        float2 f1 = __bfloat1622float2(*(__nv_bfloat162*)&pk.y);
        float2 f2 = __bfloat1622float2(*(__nv_bfloat162*)&pk.z);
        float2 f3 = __bfloat1622float2(*(__nv_bfloat162*)&pk.w);
        a0.x += f0.x; a0.y += f0.y; a1.x += f1.x; a1.y += f1.y;
        a2.x += f2.x; a2.y += f2.y; a3.x += f3.x; a3.y += f3.y;

        float di = g_dinv[w];
        float4 bA = *(const float4*)&bias[ch0];
        float4 bB = *(const float4*)&bias[ch0 + 4];
        float o0 = fmaxf(fmaf(a0.x, di, bA.x), 0.f);
        float o1 = fmaxf(fmaf(a0.y, di, bA.y), 0.f);
        float o2 = fmaxf(fmaf(a1.x, di, bA.z), 0.f);
        float o3 = fmaxf(fmaf(a1.y, di, bA.w), 0.f);
        float o4 = fmaxf(fmaf(a2.x, di, bB.x), 0.f);
        float o5 = fmaxf(fmaf(a2.y, di, bB.y), 0.f);
        float o6 = fmaxf(fmaf(a3.x, di, bB.z), 0.f);
        float o7 = fmaxf(fmaf(a3.y, di, bB.w), 0.f);
        if (OUT_BF16) {
            __nv_bfloat162 p0 = __floats2bfloat162_rn(o0, o1);
            __nv_bfloat162 p1 = __floats2bfloat162_rn(o2, o3);
            __nv_bfloat162 p2 = __floats2bfloat162_rn(o4, o5);
            __nv_bfloat162 p3 = __floats2bfloat162_rn(o6, o7);
            uint4 pko;
            pko.x = *(uint32_t*)&p0; pko.y = *(uint32_t*)&p1;
            pko.z = *(uint32_t*)&p2; pko.w = *(uint32_t*)&p3;
            *(uint4*)&g_hb[w * HID + ch0] = pko;
        } else {
            *(float4*)&g_buf0[w * HID + ch0]     = make_float4(o0, o1, o2, o3);
            *(float4*)&g_buf0[w * HID + ch0 + 4] = make_float4(o4, o5, o6, o7);
        }
    }
}

// ---------------------------------------------------------------- Pool + head (fused)
__global__ void poolfc_k(const int* __restrict__ batch,
                         const float* __restrict__ fc1w, const float* __restrict__ fc1b,
                         const float* __restrict__ fc2w, const float* __restrict__ fc2b,
                         float* __restrict__ out) {
    int g = blockIdx.x, t = threadIdx.x;   // 128 blocks x 256 thr
    __shared__ int lo_s, hi_s;
    if (t == 0) {
        int lo = 0, hi = N_NODES;
        while (lo < hi) { int m = (lo + hi) >> 1; if (batch[m] < g) lo = m + 1; else hi = m; }
        lo_s = lo;
        int lo2 = lo, hi2 = N_NODES;
        while (lo2 < hi2) { int m = (lo2 + hi2) >> 1; if (batch[m] < g + 1) lo2 = m + 1; else hi2 = m; }
        hi_s = lo2;
    }
    __syncthreads();
    int lo = lo_s, hi = hi_s;
    int c = t & 63, rg = t >> 6;
    float acc = 0.f;
    for (int r = lo + rg; r < hi; r += 4) acc += g_buf0[r * HID + c];
    __shared__ float sh[256];
    __shared__ float p[64];
    sh[t] = acc;
    __syncthreads();
    if (t < 64) {
        float s = sh[t] + sh[t + 64] + sh[t + 128] + sh[t + 192];
        float cntf = (float)(hi - lo);
        if (cntf < 1.f) cntf = 1.f;
        p[t] = s / cntf;
    }
    __syncthreads();
    float v = 0.f;
    if (t < DENSE) {
        float a = fc1b[t];
#pragma unroll
        for (int k = 0; k < 64; k++) a = fmaf(p[k], fc1w[k * DENSE + t], a);
        v = fmaxf(a, 0.f) * fc2w[t];
    }
    __syncthreads();
    sh[t] = v;
    __syncthreads();
    if (t < 64) sh[t] += sh[t + 64];
    __syncthreads();
    if (t < 32) {
        float s = sh[t] + sh[t + 32];
#pragma unroll
        for (int off = 16; off; off >>= 1) s += __shfl_down_sync(0xffffffffu, s, off);
        if (t == 0) out[g] = s + fc2b[0];
    }
}

// ---------------------------------------------------------------- launch
extern "C" void kernel_launch(void* const* d_in, const int* in_sizes, int n_in,
                              void* d_out, int out_size) {
    const float* x     = (const float*)d_in[0];
    const int*   ei    = (const int*)d_in[1];
    const int*   batch = (const int*)d_in[2];
    const float* W0    = (const float*)d_in[3];
    const float* b0    = (const float*)d_in[4];
    const float* W1    = (const float*)d_in[5];
    const float* b1    = (const float*)d_in[6];
    const float* W2    = (const float*)d_in[7];
    const float* b2    = (const float*)d_in[8];
    const float* fc1w  = (const float*)d_in[9];
    const float* fc1b  = (const float*)d_in[10];
    const float* fc2w  = (const float*)d_in[11];
    const float* fc2b  = (const float*)d_in[12];
    float* out = (float*)d_out;

    // Fused CSR build (hist -> scan -> fill in one persistent kernel)
    csr_k<<<CSR_BLOCKS, CSR_THREADS>>>(ei, x);

    const int AGG_BLOCKS  = (N_NODES * 32 + 255) / 256;   // 1 warp per node
    const int GEMM_BLOCKS = (N_NODES + 127) / 128;

    // Layer 0 (fused 3-ch aggregate + dense, bf16 out)
    agg_x_gemm0_k<<<(N_NODES * 8 + 255) / 256, 256>>>(W0, b0);
    // Layer 1
    gemm64_k<<<GEMM_BLOCKS, 256>>>(W1);
    agg_k<true><<<AGG_BLOCKS, 256>>>(b1);
    // Layer 2
    gemm64_k<<<GEMM_BLOCKS, 256>>>(W2);
    agg_k<false><<<AGG_BLOCKS, 256>>>(b2);

    // Pool + head
    poolfc_k<<<NGRAPH, 256>>>(batch, fc1w, fc1b, fc2w, fc2b, out);
}

// round 13
// speedup vs baseline: 1.1512x; 1.0002x over previous
#include <cuda_runtime.h>
#include <cuda_bf16.h>
#include <cstdint>

#define N_NODES 100000
#define N_EDGES 1600000
#define HID 64
#define NGRAPH 128
#define DENSE 128
#define SCAN_BLK 4096
#define NB ((N_NODES + SCAN_BLK - 1) / SCAN_BLK)   // 25 blocks (all co-resident)

// Scratch
__device__ float           g_buf0[N_NODES * HID];  // fp32 h (layer-2 agg out, pool input)
__device__ __nv_bfloat16   g_hb[N_NODES * HID];    // bf16 h (gemm input)
__device__ __nv_bfloat16   g_gath[N_NODES * HID];  // (h@W)*dinv, bf16 gather buffer
__device__ int    g_cnt[N_NODES];                  // zeroed at end of fill_k each call
__device__ int    g_rowptr[N_NODES + 1];
__device__ int    g_cursor[N_NODES];
__device__ int    g_col[N_EDGES];
__device__ float  g_dinv[N_NODES];
__device__ float4 g_xd[N_NODES];                   // x * dinv[src], padded
__device__ unsigned long long g_aggflag[NB];       // (1<<40)|aggregate; zeroed in fill_k

#define AGG_FLAG (1ull << 40)

// ---------------------------------------------------------------- CSR build
__global__ void hist_k(const int* __restrict__ ei) {
    int i = blockIdx.x * blockDim.x + threadIdx.x;
    if (i < N_EDGES / 4) {
        int4 d = ((const int4*)(ei + N_EDGES))[i];
        atomicAdd(&g_cnt[d.x], 1);
        atomicAdd(&g_cnt[d.y], 1);
        atomicAdd(&g_cnt[d.z], 1);
        atomicAdd(&g_cnt[d.w], 1);
    }
}

// Single-pass scan: local exclusive scan + cross-block offset via flagged
// aggregates (all NB=25 blocks co-resident -> no deadlock).
__global__ void scan_k(const float* __restrict__ x) {
    __shared__ int sh[1024];
    __shared__ int off_s;
    int tid = threadIdx.x;
    int bid = blockIdx.x;
    int base = bid * SCAN_BLK;
    int v[4];
    int local = 0;
#pragma unroll
    for (int q = 0; q < 4; q++) {
        int i = base + tid * 4 + q;
        v[q] = (i < N_NODES) ? g_cnt[i] : 0;
        local += v[q];
    }
    sh[tid] = local;
    for (int off = 1; off < 1024; off <<= 1) {
        __syncthreads();
        int t = (tid >= off) ? sh[tid - off] : 0;
        __syncthreads();
        sh[tid] += t;
    }
    __syncthreads();
    int total = sh[1023];

    if (tid < 32) {
        if (tid == 0) {
            __threadfence();
            g_aggflag[bid] = AGG_FLAG | (unsigned long long)total;
        }
        unsigned long long av = 0;
        if (tid < bid) {
            volatile unsigned long long* p = &g_aggflag[tid];
            do { av = *p; } while (!(av & AGG_FLAG));
        }
        int pre = (int)(av & 0xFFFFFFFFull);
#pragma unroll
        for (int o = 16; o; o >>= 1) pre += __shfl_xor_sync(0xffffffffu, pre, o);
        if (tid == 0) off_s = pre;
    }
    __syncthreads();
    int run = off_s + sh[tid] - local;
#pragma unroll
    for (int q = 0; q < 4; q++) {
        int i = base + tid * 4 + q;
        if (i < N_NODES) {
            g_rowptr[i] = run;
            g_cursor[i] = run;
            run += v[q];
            float di = rsqrtf((float)(v[q] + 1));   // +1 self loop
            g_dinv[i] = di;
            float x0 = x[i * 3 + 0], x1 = x[i * 3 + 1], x2 = x[i * 3 + 2];
            g_xd[i] = make_float4(x0 * di, x1 * di, x2 * di, 0.f);
        }
    }
    if (bid == NB - 1 && tid == 1023) g_rowptr[N_NODES] = run;
}

// Cursor-based fill, 4 edges per thread; re-zeroes g_cnt + aggflags at tail.
__global__ void fill_k(const int* __restrict__ ei) {
    int i = blockIdx.x * blockDim.x + threadIdx.x;
    if (i < N_EDGES / 4) {
        int4 s = ((const int4*)ei)[i];
        int4 d = ((const int4*)(ei + N_EDGES))[i];
        g_col[atomicAdd(&g_cursor[d.x], 1)] = s.x;
        g_col[atomicAdd(&g_cursor[d.y], 1)] = s.y;
        g_col[atomicAdd(&g_cursor[d.z], 1)] = s.z;
        g_col[atomicAdd(&g_cursor[d.w], 1)] = s.w;
    }
    if (i < N_NODES / 4) ((int4*)g_cnt)[i] = make_int4(0, 0, 0, 0);
    if (i < NB) g_aggflag[i] = 0ull;
}

// ---------------------------------------------------------------- Layer 0 (fused)
// 8 lanes per node: gather-reduce xd (3ch), then emit bf16 relu(aggx@W0+b0).
__global__ void agg_x_gemm0_k(const float* __restrict__ W0, const float* __restrict__ b0) {
    __shared__ float Ws[3 * HID];
    __shared__ float Bs[HID];
    int t = threadIdx.x;
    if (t < 3 * HID) Ws[t] = W0[t];
    if (t < HID) Bs[t] = b0[t];
    __syncthreads();
    int node = (blockIdx.x * blockDim.x + t) >> 3;
    int l8   = t & 7;
    if (node >= N_NODES) return;
    int s = g_rowptr[node];
    int e = g_rowptr[node + 1];
    float ax = 0.f, ay = 0.f, az = 0.f;
    if (l8 == 0) { float4 v = g_xd[node]; ax = v.x; ay = v.y; az = v.z; }
    for (int idx = s + l8; idx < e; idx += 8) {
        float4 v = g_xd[g_col[idx]];
        ax += v.x; ay += v.y; az += v.z;
    }
#pragma unroll
    for (int off = 1; off < 8; off <<= 1) {
        ax += __shfl_xor_sync(0xffffffffu, ax, off);
        ay += __shfl_xor_sync(0xffffffffu, ay, off);
        az += __shfl_xor_sync(0xffffffffu, az, off);
    }
    float di = g_dinv[node];
    ax *= di; ay *= di; az *= di;
    int c0 = l8 * 8;
    float o[8];
#pragma unroll
    for (int q = 0; q < 8; q++) {
        int c = c0 + q;
        o[q] = fmaxf(fmaf(ax, Ws[c], fmaf(ay, Ws[HID + c], fmaf(az, Ws[2 * HID + c], Bs[c]))), 0.f);
    }
    __nv_bfloat162 p0 = __floats2bfloat162_rn(o[0], o[1]);
    __nv_bfloat162 p1 = __floats2bfloat162_rn(o[2], o[3]);
    __nv_bfloat162 p2 = __floats2bfloat162_rn(o[4], o[5]);
    __nv_bfloat162 p3 = __floats2bfloat162_rn(o[6], o[7]);
    uint4 pk;
    pk.x = *(uint32_t*)&p0; pk.y = *(uint32_t*)&p1;
    pk.z = *(uint32_t*)&p2; pk.w = *(uint32_t*)&p3;
    *(uint4*)&g_hb[node * HID + c0] = pk;
}

// ---------------------------------------------------------------- GEMM (tensor core)
// g_gath[r] = bf16( (hb @ W)[r] * dinv[r] ), hb bf16, W fp32->bf16, fp32 accum.
#define AS_LD 72   // bf16 stride (64 + 8 pad)
__global__ void gemm64_k(const float* __restrict__ W) {
    __shared__ __nv_bfloat16 As[128 * AS_LD];
    __shared__ __nv_bfloat16 Wsm[64 * AS_LD];
    int t = threadIdx.x;
    int warp = t >> 5, lane = t & 31;
    int rb = blockIdx.x * 128;

#pragma unroll
    for (int q = 0; q < 16; q++) {
        int i = t + q * 256;
        int r = i >> 6, c = i & 63;
        Wsm[r * AS_LD + c] = __float2bfloat16(W[i]);
    }
#pragma unroll
    for (int q = 0; q < 4; q++) {
        int i = t + q * 256;
        int r = i >> 3, seg = i & 7;
        uint4 v = make_uint4(0, 0, 0, 0);
        if (rb + r < N_NODES) v = ((const uint4*)&g_hb[(rb + r) * HID])[seg];
        *(uint4*)&As[r * AS_LD + seg * 8] = v;
    }
    __syncthreads();

    int wrow = warp * 16;
    float acc[8][4];
#pragma unroll
    for (int nb = 0; nb < 8; nb++)
#pragma unroll
        for (int q = 0; q < 4; q++) acc[nb][q] = 0.f;

#pragma unroll
    for (int ks = 0; ks < 4; ks++) {
        uint32_t a0, a1, a2, a3;
        {
            const __nv_bfloat16* ap = &As[(wrow + (lane & 15)) * AS_LD + ks * 16 + (lane >> 4) * 8];
            uint32_t addr = (uint32_t)__cvta_generic_to_shared(ap);
            asm volatile("ldmatrix.sync.aligned.m8n8.x4.shared.b16 {%0,%1,%2,%3}, [%4];"
                         : "=r"(a0), "=r"(a1), "=r"(a2), "=r"(a3) : "r"(addr));
        }
#pragma unroll
        for (int nb = 0; nb < 8; nb++) {
            uint32_t b0, b1;
            const __nv_bfloat16* bp = &Wsm[(ks * 16 + (lane & 15)) * AS_LD + nb * 8];
            uint32_t baddr = (uint32_t)__cvta_generic_to_shared(bp);
            asm volatile("ldmatrix.sync.aligned.m8n8.x2.trans.shared.b16 {%0,%1}, [%2];"
                         : "=r"(b0), "=r"(b1) : "r"(baddr));
            asm volatile(
                "mma.sync.aligned.m16n8k16.row.col.f32.bf16.bf16.f32 "
                "{%0,%1,%2,%3},{%4,%5,%6,%7},{%8,%9},{%0,%1,%2,%3};"
                : "+f"(acc[nb][0]), "+f"(acc[nb][1]), "+f"(acc[nb][2]), "+f"(acc[nb][3])
                : "r"(a0), "r"(a1), "r"(a2), "r"(a3), "r"(b0), "r"(b1));
        }
    }

    int r0 = rb + wrow + (lane >> 2);
    int r1 = r0 + 8;
    float di0 = (r0 < N_NODES) ? g_dinv[r0] : 0.f;
    float di1 = (r1 < N_NODES) ? g_dinv[r1] : 0.f;
    int cb = (lane & 3) * 2;
#pragma unroll
    for (int nb = 0; nb < 8; nb++) {
        int c = nb * 8 + cb;
        if (r0 < N_NODES) {
            __nv_bfloat162 p = __floats2bfloat162_rn(acc[nb][0] * di0, acc[nb][1] * di0);
            *(uint32_t*)&g_gath[r0 * HID + c] = *(uint32_t*)&p;
        }
        if (r1 < N_NODES) {
            __nv_bfloat162 p = __floats2bfloat162_rn(acc[nb][2] * di1, acc[nb][3] * di1);
            *(uint32_t*)&g_gath[r1 * HID + c] = *(uint32_t*)&p;
        }
    }
}

// ---------------------------------------------------------------- Aggregation
// One warp per dst node; 4 groups x 8 lanes, direct g_col loads.
// Main loop: 4 rows per group summed as a bf16 HADD2 tree, one fp32
// convert+add per 4 edges. Remainder: exact fp32 path.
__device__ __forceinline__ __nv_bfloat162 badd2(uint32_t a, uint32_t b) {
    return __hadd2(*(__nv_bfloat162*)&a, *(__nv_bfloat162*)&b);
}

template <bool OUT_BF16>
__global__ void agg_k(const float* __restrict__ bias) {
    int w    = (blockIdx.x * blockDim.x + threadIdx.x) >> 5;
    int lane = threadIdx.x & 31;
    if (w >= N_NODES) return;
    int grp = lane >> 3;
    int l8  = lane & 7;
    int ch0 = l8 * 8;
    int s = g_rowptr[w];
    int e = g_rowptr[w + 1];

    float2 a0 = make_float2(0.f, 0.f), a1 = a0, a2 = a0, a3 = a0;

    int idx = s + grp;
    // 4-edge bf16 tree per group iteration (16 edges/warp-iter)
    for (; idx + 12 < e; idx += 16) {
        int s0 = g_col[idx];
        int s1 = g_col[idx + 4];
        int s2 = g_col[idx + 8];
        int s3 = g_col[idx + 12];
        uint4 q0 = *(const uint4*)&g_gath[s0 * HID + ch0];
        uint4 q1 = *(const uint4*)&g_gath[s1 * HID + ch0];
        uint4 q2 = *(const uint4*)&g_gath[s2 * HID + ch0];
        uint4 q3 = *(const uint4*)&g_gath[s3 * HID + ch0];
        __nv_bfloat162 tx = __hadd2(badd2(q0.x, q1.x), badd2(q2.x, q3.x));
        __nv_bfloat162 ty = __hadd2(badd2(q0.y, q1.y), badd2(q2.y, q3.y));
        __nv_bfloat162 tz = __hadd2(badd2(q0.z, q1.z), badd2(q2.z, q3.z));
        __nv_bfloat162 tw = __hadd2(badd2(q0.w, q1.w), badd2(q2.w, q3.w));
        float2 f0 = __bfloat1622float2(tx);
        float2 f1 = __bfloat1622float2(ty);
        float2 f2 = __bfloat1622float2(tz);
        float2 f3 = __bfloat1622float2(tw);
        a0.x += f0.x; a0.y += f0.y; a1.x += f1.x; a1.y += f1.y;
        a2.x += f2.x; a2.y += f2.y; a3.x += f3.x; a3.y += f3.y;
    }
    // remainder: exact fp32 path
    for (; idx < e; idx += 4) {
        int s0 = g_col[idx];
        uint4 pk = *(const uint4*)&g_gath[s0 * HID + ch0];
        float2 f0 = __bfloat1622float2(*(__nv_bfloat162*)&pk.x);
        float2 f1 = __bfloat1622float2(*(__nv_bfloat162*)&pk.y);
        float2 f2 = __bfloat1622float2(*(__nv_bfloat162*)&pk.z);
        float2 f3 = __bfloat1622float2(*(__nv_bfloat162*)&pk.w);
        a0.x += f0.x; a0.y += f0.y; a1.x += f1.x; a1.y += f1.y;
        a2.x += f2.x; a2.y += f2.y; a3.x += f3.x; a3.y += f3.y;
    }

#pragma unroll
    for (int off = 8; off <= 16; off <<= 1) {
        a0.x += __shfl_xor_sync(0xffffffffu, a0.x, off);
        a0.y += __shfl_xor_sync(0xffffffffu, a0.y, off);
        a1.x += __shfl_xor_sync(0xffffffffu, a1.x, off);
        a1.y += __shfl_xor_sync(0xffffffffu, a1.y, off);
        a2.x += __shfl_xor_sync(0xffffffffu, a2.x, off);
        a2.y += __shfl_xor_sync(0xffffffffu, a2.y, off);
        a3.x += __shfl_xor_sync(0xffffffffu, a3.x, off);
        a3.y += __shfl_xor_sync(0xffffffffu, a3.y, off);
    }

    if (grp == 0) {
        uint4 pk = *(const uint4*)&g_gath[w * HID + ch0];   // self loop (fp32 path)
        float2 f0 = __bfloat1622float2(*(__nv_bfloat162*)&pk.x);
        float2 f1 = __bfloat1622float2(*(__nv_bfloat162*)&pk.y);
        float2 f2 = __bfloat1622float2(*(__nv_bfloat162*)&pk.z);
        float2 f3 = __bfloat1622float2(*(__nv_bfloat162*)&pk.w);
        a0.x += f0.x; a0.y += f0.y; a1.x += f1.x; a1.y += f1.y;
        a2.x += f2.x; a2.y += f2.y; a3.x += f3.x; a3.y += f3.y;

        float di = g_dinv[w];
        float4 bA = *(const float4*)&bias[ch0];
        float4 bB = *(const float4*)&bias[ch0 + 4];
        float o0 = fmaxf(fmaf(a0.x, di, bA.x), 0.f);
        float o1 = fmaxf(fmaf(a0.y, di, bA.y), 0.f);
        float o2 = fmaxf(fmaf(a1.x, di, bA.z), 0.f);
        float o3 = fmaxf(fmaf(a1.y, di, bA.w), 0.f);
        float o4 = fmaxf(fmaf(a2.x, di, bB.x), 0.f);
        float o5 = fmaxf(fmaf(a2.y, di, bB.y), 0.f);
        float o6 = fmaxf(fmaf(a3.x, di, bB.z), 0.f);
        float o7 = fmaxf(fmaf(a3.y, di, bB.w), 0.f);
        if (OUT_BF16) {
            __nv_bfloat162 p0 = __floats2bfloat162_rn(o0, o1);
            __nv_bfloat162 p1 = __floats2bfloat162_rn(o2, o3);
            __nv_bfloat162 p2 = __floats2bfloat162_rn(o4, o5);
            __nv_bfloat162 p3 = __floats2bfloat162_rn(o6, o7);
            uint4 pko;
            pko.x = *(uint32_t*)&p0; pko.y = *(uint32_t*)&p1;
            pko.z = *(uint32_t*)&p2; pko.w = *(uint32_t*)&p3;
            *(uint4*)&g_hb[w * HID + ch0] = pko;
        } else {
            *(float4*)&g_buf0[w * HID + ch0]     = make_float4(o0, o1, o2, o3);
            *(float4*)&g_buf0[w * HID + ch0 + 4] = make_float4(o4, o5, o6, o7);
        }
    }
}

// ---------------------------------------------------------------- Pool + head (fused)
__global__ void poolfc_k(const int* __restrict__ batch,
                         const float* __restrict__ fc1w, const float* __restrict__ fc1b,
                         const float* __restrict__ fc2w, const float* __restrict__ fc2b,
                         float* __restrict__ out) {
    int g = blockIdx.x, t = threadIdx.x;   // 128 blocks x 256 thr
    __shared__ int lo_s, hi_s;
    if (t == 0) {
        int lo = 0, hi = N_NODES;
        while (lo < hi) { int m = (lo + hi) >> 1; if (batch[m] < g) lo = m + 1; else hi = m; }
        lo_s = lo;
        int lo2 = lo, hi2 = N_NODES;
        while (lo2 < hi2) { int m = (lo2 + hi2) >> 1; if (batch[m] < g + 1) lo2 = m + 1; else hi2 = m; }
        hi_s = lo2;
    }
    __syncthreads();
    int lo = lo_s, hi = hi_s;
    int c = t & 63, rg = t >> 6;
    float acc = 0.f;
    for (int r = lo + rg; r < hi; r += 4) acc += g_buf0[r * HID + c];
    __shared__ float sh[256];
    __shared__ float p[64];
    sh[t] = acc;
    __syncthreads();
    if (t < 64) {
        float s = sh[t] + sh[t + 64] + sh[t + 128] + sh[t + 192];
        float cntf = (float)(hi - lo);
        if (cntf < 1.f) cntf = 1.f;
        p[t] = s / cntf;
    }
    __syncthreads();
    float v = 0.f;
    if (t < DENSE) {
        float a = fc1b[t];
#pragma unroll
        for (int k = 0; k < 64; k++) a = fmaf(p[k], fc1w[k * DENSE + t], a);
        v = fmaxf(a, 0.f) * fc2w[t];
    }
    __syncthreads();
    sh[t] = v;
    __syncthreads();
    if (t < 64) sh[t] += sh[t + 64];
    __syncthreads();
    if (t < 32) {
        float s = sh[t] + sh[t + 32];
#pragma unroll
        for (int off = 16; off; off >>= 1) s += __shfl_down_sync(0xffffffffu, s, off);
        if (t == 0) out[g] = s + fc2b[0];
    }
}

// ---------------------------------------------------------------- launch
extern "C" void kernel_launch(void* const* d_in, const int* in_sizes, int n_in,
                              void* d_out, int out_size) {
    const float* x     = (const float*)d_in[0];
    const int*   ei    = (const int*)d_in[1];
    const int*   batch = (const int*)d_in[2];
    const float* W0    = (const float*)d_in[3];
    const float* b0    = (const float*)d_in[4];
    const float* W1    = (const float*)d_in[5];
    const float* b1    = (const float*)d_in[6];
    const float* W2    = (const float*)d_in[7];
    const float* b2    = (const float*)d_in[8];
    const float* fc1w  = (const float*)d_in[9];
    const float* fc1b  = (const float*)d_in[10];
    const float* fc2w  = (const float*)d_in[11];
    const float* fc2b  = (const float*)d_in[12];
    float* out = (float*)d_out;

    // CSR build (g_cnt and g_aggflag enter zeroed: zero-init at load,
    // re-zeroed by fill_k each call)
    hist_k<<<(N_EDGES / 4 + 255) / 256, 256>>>(ei);
    scan_k<<<NB, 1024>>>(x);
    fill_k<<<(N_EDGES / 4 + 255) / 256, 256>>>(ei);

    const int AGG_BLOCKS  = (N_NODES * 32 + 255) / 256;   // 1 warp per node
    const int GEMM_BLOCKS = (N_NODES + 127) / 128;

    // Layer 0 (fused 3-ch aggregate + dense, bf16 out)
    agg_x_gemm0_k<<<(N_NODES * 8 + 255) / 256, 256>>>(W0, b0);
    // Layer 1
    gemm64_k<<<GEMM_BLOCKS, 256>>>(W1);
    agg_k<true><<<AGG_BLOCKS, 256>>>(b1);
    // Layer 2
    gemm64_k<<<GEMM_BLOCKS, 256>>>(W2);
    agg_k<false><<<AGG_BLOCKS, 256>>>(b2);

    // Pool + head
    poolfc_k<<<NGRAPH, 256>>>(batch, fc1w, fc1b, fc2w, fc2b, out);
}